// round 14
// baseline (speedup 1.0000x reference)
#include <cuda_runtime.h>
#include <cuda_fp16.h>
#include <math.h>
#include <stdint.h>

#define BB 16384
#define HH 256
#define STEPS 120
#define OUT_ 31
#define YSTRIDE (STEPS*OUT_)

// ---- gru GEMM tiling: CTA = 64 rows x 256 gate cols; K staged at 16, 4-stage pipeline ----
#define ST   24            // smem row stride in halves (16 data + 8 pad)
#define A_OFF   0u
#define BHI_OFF 3072u      // A stage = 64*24*2 = 3072 B
#define BLO_OFF 15360u     // Bhi = 256*24*2 = 12288 B
#define BUFB    27648u     // stage total
#define NSTAGE  4
#define SMEM_ALLOC 110592  // 4 stages; 2 CTAs/SM = 221 KB <= 227 KB

// ---- fused y-projection (blockIdx.y==4): M=64, N=32, K=256 ----
#define OP_ST 264
#define FYA_OFF 0u
#define FYW_OFF 33792u     // A = 64*264*2; + W 32*264*2 -> 50688 <= SMEM_ALLOC

// ---- standalone final out_proj: M=64/CTA, block=128 ----
#define OPA_OFF 0u
#define OPW_OFF 33792u
#define OP_SMEM 50688u

// ---------------- device scratch (no allocs allowed) ----------------
__device__ __half g_Whi [4*HH*HH];   // combined gate weights hi, steps>=1
__device__ __half g_Wlo [4*HH*HH];   // lo residual (W - hi)
__device__ __half g_Whi0[4*HH*HH];   // step-0 variant (x=0)
__device__ __half g_Wlo0[4*HH*HH];
__device__ __half g_WoutH[32*HH];    // fp16 Wout, row 31 zero-padded
__device__ float g_b4[4*HH];
__device__ float g_hA[BB*HH];
__device__ float g_hB[BB*HH];
__device__ __half g_s0[BB*HH], g_s1[BB*HH];

// ---------------- PTX helpers (family-safe: sm_80-era only) ----------------
__device__ __forceinline__ uint32_t smem_u32(const void* p) {
    uint32_t a;
    asm("{ .reg .u64 t; cvta.to.shared.u64 t, %1; cvt.u32.u64 %0, t; }" : "=r"(a) : "l"(p));
    return a;
}
__device__ __forceinline__ void cpa16(uint32_t dst, const void* src) {
    asm volatile("cp.async.cg.shared.global [%0], [%1], 16;" :: "r"(dst), "l"(src) : "memory");
}
__device__ __forceinline__ void ldm4(uint32_t* r, uint32_t addr) {
    asm volatile("ldmatrix.sync.aligned.m8n8.x4.shared.b16 {%0,%1,%2,%3}, [%4];"
                 : "=r"(r[0]), "=r"(r[1]), "=r"(r[2]), "=r"(r[3]) : "r"(addr));
}
__device__ __forceinline__ void mma16816(float* c, const uint32_t* a, const uint32_t* b) {
    asm volatile("mma.sync.aligned.m16n8k16.row.col.f32.f16.f16.f32 "
                 "{%0,%1,%2,%3}, {%4,%5,%6,%7}, {%8,%9}, {%0,%1,%2,%3};"
                 : "+f"(c[0]), "+f"(c[1]), "+f"(c[2]), "+f"(c[3])
                 : "r"(a[0]), "r"(a[1]), "r"(a[2]), "r"(a[3]), "r"(b[0]), "r"(b[1]));
}

// ---------------- prep: combined weights, fp16 hi/lo split; Wout fp16 ----------------
__global__ void prep_kernel(const float* __restrict__ Wih, const float* __restrict__ Whh,
                            const float* __restrict__ bih, const float* __restrict__ bhh,
                            const float* __restrict__ Wout)
{
    int idx = blockIdx.x * blockDim.x + threadIdx.x;
    if (idx < 4*HH*HH) {
        int j = idx / HH;
        int k = idx % HH;
        int g = j >> 8, c = j & 255;
        float w, w0;
        if (g == 0)      { float a = Wih[c*HH+k],       b = Whh[c*HH+k];       w = a + b; w0 = b; }
        else if (g == 1) { float a = Wih[(256+c)*HH+k], b = Whh[(256+c)*HH+k]; w = a + b; w0 = b; }
        else if (g == 2) { w = Wih[(512+c)*HH+k]; w0 = 0.f; }
        else             { w = Whh[(512+c)*HH+k]; w0 = w;  }
        __half hi = __float2half_rn(w);
        g_Whi[idx] = hi;
        g_Wlo[idx] = __float2half_rn(w - __half2float(hi));
        __half hi0 = __float2half_rn(w0);
        g_Whi0[idx] = hi0;
        g_Wlo0[idx] = __float2half_rn(w0 - __half2float(hi0));
    }
    if (idx < 32*HH) {
        int o = idx >> 8, k = idx & 255;
        g_WoutH[idx] = __float2half_rn(o < OUT_ ? Wout[o*HH + k] : 0.f);
    }
    if (idx < 4*HH) {
        int g = idx >> 8, c = idx & 255;
        float b;
        if (g == 0)      b = bih[c]     + bhh[c];
        else if (g == 1) b = bih[256+c] + bhh[256+c];
        else if (g == 2) b = bih[512+c];
        else             b = bhh[512+c];
        g_b4[idx] = b;
    }
}

__global__ void split_kernel(const float* __restrict__ h, __half* __restrict__ o)
{
    int idx = blockIdx.x * blockDim.x + threadIdx.x;
    if (idx < BB*HH) o[idx] = __float2half_rn(h[idx]);
}

// ---------------- fused GRU step + previous-step y projection ----------------
// grid = (256, 5), 256 threads (8 warps), 2 CTAs/SM, 4-stage K=16 cp.async pipeline.
__global__ void __launch_bounds__(256, 2)
gru_mma_kernel(const __half* __restrict__ Ah,
               const __half* __restrict__ Whi, const __half* __restrict__ Wlo,
               const float* __restrict__ hprev, float* __restrict__ hout,
               __half* __restrict__ Oh,
               const float* __restrict__ bout, float* __restrict__ y, int step)
{
    extern __shared__ __align__(16) char dsm[];
    const uint32_t sb = smem_u32(dsm);

    const int tid  = threadIdx.x;
    const int lane = tid & 31;
    const int warp = tid >> 5;
    const int row0 = blockIdx.x * 64;

    if (blockIdx.y == 4) {
        // ---------- y-projection block: M=64, N=32, K=256 ----------
        if (step == 0) return;
#pragma unroll
        for (int i = 0; i < 8; i++) {
            int e = tid + i * 256;
            int r = e >> 5, seg = e & 31;
            cpa16(sb + FYA_OFF + (uint32_t)(r*OP_ST + seg*8)*2,
                  Ah + (size_t)(row0 + r)*HH + seg*8);
        }
#pragma unroll
        for (int i = 0; i < 4; i++) {
            int e = tid + i * 256;
            int r = e >> 5, seg = e & 31;
            cpa16(sb + FYW_OFF + (uint32_t)(r*OP_ST + seg*8)*2,
                  g_WoutH + (size_t)r*HH + seg*8);
        }
        asm volatile("cp.async.commit_group;" ::: "memory");
        asm volatile("cp.async.wait_group 0;" ::: "memory");
        __syncthreads();

        const int mt = warp >> 1;
        const int nh = warp & 1;
        const int aRow  = mt*16 + (lane & 15);
        const int aKoff = (lane >> 4) * 8;
        const int bRow  = nh*16 + (lane >> 4) * 8 + (lane & 7);
        const int bKoff = ((lane >> 3) & 1) * 8;

        float acc[2][4];
#pragma unroll
        for (int nt = 0; nt < 2; nt++)
#pragma unroll
            for (int q = 0; q < 4; q++) acc[nt][q] = 0.f;

#pragma unroll
        for (int ks = 0; ks < 16; ks++) {
            uint32_t ah[4], bh[4];
            ldm4(ah, sb + FYA_OFF + (uint32_t)(aRow*OP_ST + ks*16 + aKoff)*2);
            ldm4(bh, sb + FYW_OFF + (uint32_t)(bRow*OP_ST + ks*16 + bKoff)*2);
#pragma unroll
            for (int nt = 0; nt < 2; nt++)
                mma16816(acc[nt], ah, &bh[nt*2]);
        }

        const int rl = mt*16 + (lane >> 2);
        const int cb = (lane & 3) * 2;
#pragma unroll
        for (int nt = 0; nt < 2; nt++) {
            int col = nh*16 + nt*8 + cb;
            float b0 = bout[col];
            size_t base0 = (size_t)(row0 + rl) * YSTRIDE + (size_t)(step - 1) * OUT_;
            size_t base1 = base0 + 8u * YSTRIDE;
            y[base0 + col] = acc[nt][0] + b0;
            y[base1 + col] = acc[nt][2] + b0;
            if (col < 30) {
                float b1 = bout[col + 1];
                y[base0 + col + 1] = acc[nt][1] + b1;
                y[base1 + col + 1] = acc[nt][3] + b1;
            }
        }
        return;
    }

    // ---------- gru GEMM block: 64 rows, 8 warps = 8 hidden-col chunks ----------
    const int wn   = warp;             // 0..7 -> hidden col chunk wn*8
    const int col0 = blockIdx.y * 64;

    const int aRow  = lane & 15;
    const int aKoff = (lane >> 4) * 8;

    const int lg = lane >> 3, lr = lane & 7;
    const int bRowOff = (((lg >> 1) * 64) + wn*8 + lr) * ST + (lg & 1) * 8;

    float acc[4][4][4];   // [mt][gate][q]
#pragma unroll
    for (int mt = 0; mt < 4; mt++)
#pragma unroll
        for (int g = 0; g < 4; g++)
#pragma unroll
            for (int q = 0; q < 4; q++) acc[mt][g][q] = 0.f;

    // stage loader: K=16 slice s. A: 128 chunks (tid<128); B: 512 chunks/term, 2+2 per thread
    auto load_stage = [&](int s) {
        const uint32_t bufoff = (uint32_t)(s & (NSTAGE-1)) * BUFB;
        const int kb = s * 16;
        if (tid < 128) {
            int r = tid >> 1, seg = tid & 1;
            uint32_t d = sb + bufoff + A_OFF + (uint32_t)(r*ST + seg*8) * 2;
            cpa16(d, Ah + (size_t)(row0 + r) * HH + kb + seg*8);
        }
#pragma unroll
        for (int i = 0; i < 2; i++) {
            int e = tid + i * 256;           // 0..511
            int n = e >> 1, seg = e & 1;
            int j = ((n >> 6) << 8) + col0 + (n & 63);
            uint32_t d = sb + bufoff + (uint32_t)(n*ST + seg*8) * 2;
            size_t go = (size_t)j * HH + kb + seg*8;
            cpa16(d + BHI_OFF, Whi + go);
            cpa16(d + BLO_OFF, Wlo + go);
        }
    };

    load_stage(0);
    asm volatile("cp.async.commit_group;" ::: "memory");
    load_stage(1);
    asm volatile("cp.async.commit_group;" ::: "memory");
    load_stage(2);
    asm volatile("cp.async.commit_group;" ::: "memory");

    for (int s = 0; s < 16; s++) {
        asm volatile("cp.async.wait_group 2;" ::: "memory");   // stage s landed
        __syncthreads();                                        // buffer (s+3)%4 reads done
        if (s < 13) {
            load_stage(s + 3);
            asm volatile("cp.async.commit_group;" ::: "memory");
        }
        const uint32_t base = sb + (uint32_t)(s & (NSTAGE-1)) * BUFB;

        uint32_t bh[8], bl[8];
        {
            uint32_t a0 = base + BHI_OFF + (uint32_t)bRowOff * 2;
            uint32_t a1 = a0 + (uint32_t)(128*ST) * 2;   // gates 2,3
            ldm4(&bh[0], a0);
            ldm4(&bh[4], a1);
            ldm4(&bl[0], a0 + (BLO_OFF - BHI_OFF));
            ldm4(&bl[4], a1 + (BLO_OFF - BHI_OFF));
        }
#pragma unroll
        for (int mt = 0; mt < 4; mt++) {
            uint32_t aaddr = base + A_OFF + (uint32_t)((aRow + mt*16)*ST + aKoff) * 2;
            uint32_t ah[4];
            ldm4(ah, aaddr);
#pragma unroll
            for (int g = 0; g < 4; g++) {
                mma16816(acc[mt][g], ah, &bh[g*2]);   // A * Whi
                mma16816(acc[mt][g], ah, &bl[g*2]);   // A * Wlo
            }
        }
    }

    // ---- in-register epilogue ----
    const int cA = wn*8 + (lane & 3)*2;
    const int cg = col0 + cA;
    const float2 br = *(const float2*)&g_b4[cg];
    const float2 bz = *(const float2*)&g_b4[256 + cg];
    const float2 bn = *(const float2*)&g_b4[512 + cg];
    const float2 bm = *(const float2*)&g_b4[768 + cg];
    const float bias[4][2] = {{br.x,br.y},{bz.x,bz.y},{bn.x,bn.y},{bm.x,bm.y}};

#pragma unroll
    for (int mt = 0; mt < 4; mt++) {
        const int rr = row0 + mt*16 + (lane >> 2);
#pragma unroll
        for (int p = 0; p < 2; p++) {
            const int r = rr + p*8;
            float2 hp = *(const float2*)(hprev + (size_t)r*HH + cg);
            float hpv[2] = {hp.x, hp.y};
            float hn[2];
#pragma unroll
            for (int j = 0; j < 2; j++) {
                int q = p*2 + j;
                float arv = acc[mt][0][q] + bias[0][j];
                float azv = acc[mt][1][q] + bias[1][j];
                float anv = acc[mt][2][q] + bias[2][j];
                float ahv = acc[mt][3][q] + bias[3][j];
                float rg = 1.f / (1.f + __expf(-arv));
                float zg = 1.f / (1.f + __expf(-azv));
                float x  = anv + rg * ahv;
                float t  = __expf(-2.f * fabsf(x));
                float th = (1.f - t) / (1.f + t);
                th = copysignf(th, x);
                hn[j] = (1.f - zg) * th + zg * hpv[j];
            }
            *(float2*)(hout + (size_t)r*HH + cg) = make_float2(hn[0], hn[1]);
            __half2 h2 = __floats2half2_rn(hn[0], hn[1]);
            *(__half2*)(Oh + (size_t)r*HH + cg) = h2;
        }
    }
}

// ---------------- standalone final out_proj: M=64/CTA, block=128 ----------------
__global__ void __launch_bounds__(128)
out_proj_kernel(const __half* __restrict__ Ah, const float* __restrict__ bout,
                float* __restrict__ y, int step)
{
    extern __shared__ __align__(16) char dsm[];
    const uint32_t sb = smem_u32(dsm);

    const int tid  = threadIdx.x;
    const int lane = tid & 31;
    const int warp = tid >> 5;
    const int row0 = blockIdx.x * 64;

#pragma unroll
    for (int i = 0; i < 16; i++) {
        int e = tid + i * 128;
        int r = e >> 5, seg = e & 31;
        cpa16(sb + OPA_OFF + (uint32_t)(r*OP_ST + seg*8)*2,
              Ah + (size_t)(row0 + r)*HH + seg*8);
    }
#pragma unroll
    for (int i = 0; i < 8; i++) {
        int e = tid + i * 128;
        int r = e >> 5, seg = e & 31;
        cpa16(sb + OPW_OFF + (uint32_t)(r*OP_ST + seg*8)*2,
              g_WoutH + (size_t)r*HH + seg*8);
    }
    asm volatile("cp.async.commit_group;" ::: "memory");
    asm volatile("cp.async.wait_group 0;" ::: "memory");
    __syncthreads();

    const int aRow  = warp*16 + (lane & 15);
    const int aKoff = (lane >> 4) * 8;
    const int bRow  = (lane >> 4) * 8 + (lane & 7);
    const int bKoff = ((lane >> 3) & 1) * 8;

    float acc[4][4];
#pragma unroll
    for (int nt = 0; nt < 4; nt++)
#pragma unroll
        for (int q = 0; q < 4; q++) acc[nt][q] = 0.f;

#pragma unroll
    for (int ks = 0; ks < 16; ks++) {
        uint32_t ah[4], bh[8];
        ldm4(ah, sb + OPA_OFF + (uint32_t)(aRow*OP_ST + ks*16 + aKoff)*2);
#pragma unroll
        for (int p = 0; p < 2; p++)
            ldm4(&bh[p*4], sb + OPW_OFF + (uint32_t)((bRow + p*16)*OP_ST + ks*16 + bKoff)*2);
#pragma unroll
        for (int nt = 0; nt < 4; nt++)
            mma16816(acc[nt], ah, &bh[nt*2]);
    }

    const int rl  = warp*16 + (lane >> 2);
    const int cb  = (lane & 3) * 2;
#pragma unroll
    for (int nt = 0; nt < 4; nt++) {
        int col = nt*8 + cb;
        float b0 = bout[col];
        size_t base0 = (size_t)(row0 + rl) * YSTRIDE + (size_t)step * OUT_;
        size_t base1 = base0 + 8u * YSTRIDE;
        y[base0 + col] = acc[nt][0] + b0;
        y[base1 + col] = acc[nt][2] + b0;
        if (col < 30) {
            float b1 = bout[col + 1];
            y[base0 + col + 1] = acc[nt][1] + b1;
            y[base1 + col + 1] = acc[nt][3] + b1;
        }
    }
}

// ---------------- host ----------------
extern "C" void kernel_launch(void* const* d_in, const int* in_sizes, int n_in,
                              void* d_out, int out_size)
{
    const float* hidden = (const float*)d_in[0];
    const float* Wih    = (const float*)d_in[1];
    const float* Whh    = (const float*)d_in[2];
    const float* bih    = (const float*)d_in[3];
    const float* bhh    = (const float*)d_in[4];
    const float* Wout   = (const float*)d_in[5];
    const float* bout   = (const float*)d_in[6];
    float* y = (float*)d_out;

    __half *pWhi, *pWlo, *pWhi0, *pWlo0, *ps0, *ps1;
    float *phA, *phB;
    cudaGetSymbolAddress((void**)&pWhi,  g_Whi);
    cudaGetSymbolAddress((void**)&pWlo,  g_Wlo);
    cudaGetSymbolAddress((void**)&pWhi0, g_Whi0);
    cudaGetSymbolAddress((void**)&pWlo0, g_Wlo0);
    cudaGetSymbolAddress((void**)&ps0,   g_s0);
    cudaGetSymbolAddress((void**)&ps1,   g_s1);
    cudaGetSymbolAddress((void**)&phA,   g_hA);
    cudaGetSymbolAddress((void**)&phB,   g_hB);

    cudaFuncSetAttribute(gru_mma_kernel, cudaFuncAttributeMaxDynamicSharedMemorySize, SMEM_ALLOC);
    cudaFuncSetAttribute(out_proj_kernel, cudaFuncAttributeMaxDynamicSharedMemorySize, OP_SMEM);

    prep_kernel<<<(4*HH*HH + 255)/256, 256>>>(Wih, Whh, bih, bhh, Wout);
    split_kernel<<<(BB*HH + 255)/256, 256>>>(hidden, ps0);

    dim3 grid(BB/64, 5);   // (256, 4 gru slices + 1 y-projection slice)

    // step 0: x=0 variant; y-slice skips (step==0)
    gru_mma_kernel<<<grid, 256, SMEM_ALLOC>>>(ps0, pWhi0, pWlo0, hidden, phA, ps1,
                                              bout, y, 0);

    float* hin = phA;  float* hot = phB;
    __half *ih = ps1, *oh = ps0;

    for (int t = 1; t < STEPS; t++) {
        gru_mma_kernel<<<grid, 256, SMEM_ALLOC>>>(ih, pWhi, pWlo, hin, hot, oh,
                                                  bout, y, t);
        float* tf = hin; hin = hot; hot = tf;
        __half* th = ih; ih = oh; oh = th;
    }
    // y_119 from final state (in `ih` after last swap)
    out_proj_kernel<<<BB/64, 128, OP_SMEM>>>(ih, bout, y, STEPS - 1);
}

// round 15
// speedup vs baseline: 1.2093x; 1.2093x over previous
#include <cuda_runtime.h>
#include <cuda_fp16.h>
#include <math.h>
#include <stdint.h>

#define BB 16384
#define HH 256
#define STEPS 120
#define OUT_ 31
#define YSTRIDE (STEPS*OUT_)

// ---- gru GEMM tiling: CTA = 64 rows x 256 gate cols (4 gates x 64 hidden cols) ----
#define ST   40            // smem row stride in halves (32 data + 8 pad)
#define A_OFF   0u
#define BHI_OFF 5120u      // A stage = 64*40*2 = 5120 B
#define BLO_OFF 25600u     // Bhi = 256*40*2 = 20480 B
#define BUFB    46080u     // stage total
#define SMEM_ALLOC 92160   // 2 stages; 2 CTAs/SM = 184 KB <= 227 KB

#define LO_SCALE 1024.0f
#define LO_INV   (1.0f/1024.0f)

// ---- fused y-projection (blockIdx.y==4): M=64, N=32, K=256 ----
#define OP_ST 264          // halves per smem row (256 + 8 pad)
#define FYA_OFF 0u
#define FYW_OFF 33792u     // A = 64*264*2; + W 32*264*2 = 16896 -> 50688 <= SMEM_ALLOC

// ---- standalone final out_proj: M=64/CTA, block=128 ----
#define OPA_OFF 0u
#define OPW_OFF 33792u
#define OP_SMEM 50688u

// ---------------- device scratch (no allocs allowed) ----------------
__device__ __half g_Whi [4*HH*HH];   // combined gate weights hi, steps>=1
__device__ __half g_Wlo [4*HH*HH];   // (W - hi) * 1024
__device__ __half g_Whi0[4*HH*HH];   // step-0 variant (x=0)
__device__ __half g_Wlo0[4*HH*HH];
__device__ __half g_WoutH[32*HH];    // fp16 Wout, row 31 zero-padded
__device__ float g_b4[4*HH];
__device__ float g_hA[BB*HH];
__device__ float g_hB[BB*HH];
__device__ __half g_s0[BB*HH], g_s1[BB*HH];

// ---------------- PTX helpers (family-safe: sm_80-era only) ----------------
__device__ __forceinline__ uint32_t smem_u32(const void* p) {
    uint32_t a;
    asm("{ .reg .u64 t; cvta.to.shared.u64 t, %1; cvt.u32.u64 %0, t; }" : "=r"(a) : "l"(p));
    return a;
}
__device__ __forceinline__ void cpa16(uint32_t dst, const void* src) {
    asm volatile("cp.async.cg.shared.global [%0], [%1], 16;" :: "r"(dst), "l"(src) : "memory");
}
__device__ __forceinline__ void ldm4(uint32_t* r, uint32_t addr) {
    asm volatile("ldmatrix.sync.aligned.m8n8.x4.shared.b16 {%0,%1,%2,%3}, [%4];"
                 : "=r"(r[0]), "=r"(r[1]), "=r"(r[2]), "=r"(r[3]) : "r"(addr));
}
// fp32-accumulator MMA (hi term)
__device__ __forceinline__ void mma16816(float* c, const uint32_t* a, const uint32_t* b) {
    asm volatile("mma.sync.aligned.m16n8k16.row.col.f32.f16.f16.f32 "
                 "{%0,%1,%2,%3}, {%4,%5,%6,%7}, {%8,%9}, {%0,%1,%2,%3};"
                 : "+f"(c[0]), "+f"(c[1]), "+f"(c[2]), "+f"(c[3])
                 : "r"(a[0]), "r"(a[1]), "r"(a[2]), "r"(a[3]), "r"(b[0]), "r"(b[1]));
}
// fp16-accumulator MMA (lo term, 2x rate on legacy HMMA path)
__device__ __forceinline__ void mma16816h(uint32_t* c, const uint32_t* a, const uint32_t* b) {
    asm volatile("mma.sync.aligned.m16n8k16.row.col.f16.f16.f16.f16 "
                 "{%0,%1}, {%2,%3,%4,%5}, {%6,%7}, {%0,%1};"
                 : "+r"(c[0]), "+r"(c[1])
                 : "r"(a[0]), "r"(a[1]), "r"(a[2]), "r"(a[3]), "r"(b[0]), "r"(b[1]));
}

// ---------------- prep: combined weights, fp16 hi/lo split (lo scaled); Wout fp16 ----------------
__global__ void prep_kernel(const float* __restrict__ Wih, const float* __restrict__ Whh,
                            const float* __restrict__ bih, const float* __restrict__ bhh,
                            const float* __restrict__ Wout)
{
    int idx = blockIdx.x * blockDim.x + threadIdx.x;
    if (idx < 4*HH*HH) {
        int j = idx / HH;
        int k = idx % HH;
        int g = j >> 8, c = j & 255;
        float w, w0;
        if (g == 0)      { float a = Wih[c*HH+k],       b = Whh[c*HH+k];       w = a + b; w0 = b; }
        else if (g == 1) { float a = Wih[(256+c)*HH+k], b = Whh[(256+c)*HH+k]; w = a + b; w0 = b; }
        else if (g == 2) { w = Wih[(512+c)*HH+k]; w0 = 0.f; }
        else             { w = Whh[(512+c)*HH+k]; w0 = w;  }
        __half hi = __float2half_rn(w);
        g_Whi[idx] = hi;
        g_Wlo[idx] = __float2half_rn((w - __half2float(hi)) * LO_SCALE);
        __half hi0 = __float2half_rn(w0);
        g_Whi0[idx] = hi0;
        g_Wlo0[idx] = __float2half_rn((w0 - __half2float(hi0)) * LO_SCALE);
    }
    if (idx < 32*HH) {
        int o = idx >> 8, k = idx & 255;
        g_WoutH[idx] = __float2half_rn(o < OUT_ ? Wout[o*HH + k] : 0.f);
    }
    if (idx < 4*HH) {
        int g = idx >> 8, c = idx & 255;
        float b;
        if (g == 0)      b = bih[c]     + bhh[c];
        else if (g == 1) b = bih[256+c] + bhh[256+c];
        else if (g == 2) b = bih[512+c];
        else             b = bhh[512+c];
        g_b4[idx] = b;
    }
}

__global__ void split_kernel(const float* __restrict__ h, __half* __restrict__ o)
{
    int idx = blockIdx.x * blockDim.x + threadIdx.x;
    if (idx < BB*HH) o[idx] = __float2half_rn(h[idx]);
}

// ---------------- fused GRU step + previous-step y projection ----------------
// grid = (256, 5), 256 threads (8 warps), 2 CTAs/SM, 2-stage K=32 pipeline (R12 shape).
//   blockIdx.y < 4 : gru GEMM (rows bx*64, hidden cols by*64), gate-interleaved warps
//   blockIdx.y == 4: y_{step-1} = Ah @ Wout^T + bout (skipped when step==0)
__global__ void __launch_bounds__(256, 2)
gru_mma_kernel(const __half* __restrict__ Ah,
               const __half* __restrict__ Whi, const __half* __restrict__ Wlo,
               const float* __restrict__ hprev, float* __restrict__ hout,
               __half* __restrict__ Oh,
               const float* __restrict__ bout, float* __restrict__ y, int step)
{
    extern __shared__ __align__(16) char dsm[];
    const uint32_t sb = smem_u32(dsm);

    const int tid  = threadIdx.x;
    const int lane = tid & 31;
    const int warp = tid >> 5;
    const int row0 = blockIdx.x * 64;

    if (blockIdx.y == 4) {
        // ---------- y-projection block: M=64, N=32, K=256 ----------
        if (step == 0) return;
#pragma unroll
        for (int i = 0; i < 8; i++) {
            int e = tid + i * 256;
            int r = e >> 5, seg = e & 31;
            cpa16(sb + FYA_OFF + (uint32_t)(r*OP_ST + seg*8)*2,
                  Ah + (size_t)(row0 + r)*HH + seg*8);
        }
#pragma unroll
        for (int i = 0; i < 4; i++) {
            int e = tid + i * 256;
            int r = e >> 5, seg = e & 31;
            cpa16(sb + FYW_OFF + (uint32_t)(r*OP_ST + seg*8)*2,
                  g_WoutH + (size_t)r*HH + seg*8);
        }
        asm volatile("cp.async.commit_group;" ::: "memory");
        asm volatile("cp.async.wait_group 0;" ::: "memory");
        __syncthreads();

        const int mt = warp >> 1;
        const int nh = warp & 1;
        const int aRow  = mt*16 + (lane & 15);
        const int aKoff = (lane >> 4) * 8;
        const int bRow  = nh*16 + (lane >> 4) * 8 + (lane & 7);
        const int bKoff = ((lane >> 3) & 1) * 8;

        float acc[2][4];
#pragma unroll
        for (int nt = 0; nt < 2; nt++)
#pragma unroll
            for (int q = 0; q < 4; q++) acc[nt][q] = 0.f;

#pragma unroll
        for (int ks = 0; ks < 16; ks++) {
            uint32_t ah[4], bh[4];
            ldm4(ah, sb + FYA_OFF + (uint32_t)(aRow*OP_ST + ks*16 + aKoff)*2);
            ldm4(bh, sb + FYW_OFF + (uint32_t)(bRow*OP_ST + ks*16 + bKoff)*2);
#pragma unroll
            for (int nt = 0; nt < 2; nt++)
                mma16816(acc[nt], ah, &bh[nt*2]);
        }

        const int rl = mt*16 + (lane >> 2);
        const int cb = (lane & 3) * 2;
#pragma unroll
        for (int nt = 0; nt < 2; nt++) {
            int col = nh*16 + nt*8 + cb;
            float b0 = bout[col];
            size_t base0 = (size_t)(row0 + rl) * YSTRIDE + (size_t)(step - 1) * OUT_;
            size_t base1 = base0 + 8u * YSTRIDE;
            y[base0 + col] = acc[nt][0] + b0;
            y[base1 + col] = acc[nt][2] + b0;
            if (col < 30) {
                float b1 = bout[col + 1];
                y[base0 + col + 1] = acc[nt][1] + b1;
                y[base1 + col + 1] = acc[nt][3] + b1;
            }
        }
        return;
    }

    // ---------- gru GEMM block: 64 rows, 8 warps = 8 hidden-col chunks ----------
    const int wn   = warp;             // 0..7 -> hidden col chunk wn*8
    const int col0 = blockIdx.y * 64;

    const int aRow  = lane & 15;
    const int aKoff = (lane >> 4) * 8;

    const int lg = lane >> 3, lr = lane & 7;
    const int bRowOff = (((lg >> 1) * 64) + wn*8 + lr) * ST + (lg & 1) * 8;

    const int ar = tid >> 2, aseg = tid & 3;   // A: 256 x 16B chunks, 1/thread

    float    accH[4][4][4];   // hi term, fp32  [mt][gate][q]
    uint32_t accL[4][4][2];   // lo term, fp16x2 [mt][gate][p]
#pragma unroll
    for (int mt = 0; mt < 4; mt++)
#pragma unroll
        for (int g = 0; g < 4; g++) {
#pragma unroll
            for (int q = 0; q < 4; q++) accH[mt][g][q] = 0.f;
            accL[mt][g][0] = 0u;
            accL[mt][g][1] = 0u;
        }

    auto load_stage = [&](int s, uint32_t bufoff) {
        const int kb = s * 32;
        {
            uint32_t d = sb + bufoff + A_OFF + (uint32_t)(ar*ST + aseg*8) * 2;
            size_t go = (size_t)(row0 + ar) * HH + kb + aseg*8;
            cpa16(d, Ah + go);
        }
#pragma unroll
        for (int i = 0; i < 4; i++) {
            int e = tid + i * 256;
            int n = e >> 2, seg = e & 3;
            int j = ((n >> 6) << 8) + col0 + (n & 63);
            uint32_t d = sb + bufoff + (uint32_t)(n*ST + seg*8) * 2;
            size_t go = (size_t)j * HH + kb + seg*8;
            cpa16(d + BHI_OFF, Whi + go);
            cpa16(d + BLO_OFF, Wlo + go);
        }
    };

    load_stage(0, 0);
    asm volatile("cp.async.commit_group;" ::: "memory");

    for (int s = 0; s < 8; s++) {
        asm volatile("cp.async.wait_group 0;" ::: "memory");
        __syncthreads();
        if (s < 7) {
            load_stage(s + 1, ((s + 1) & 1) * BUFB);
            asm volatile("cp.async.commit_group;" ::: "memory");
        }
        const uint32_t base = sb + (s & 1) * BUFB;

#pragma unroll
        for (int kc = 0; kc < 2; kc++) {
            uint32_t bh[8], bl[8];
            {
                uint32_t a0 = base + BHI_OFF + (uint32_t)(bRowOff + kc*16) * 2;
                uint32_t a1 = a0 + (uint32_t)(128*ST) * 2;   // gates 2,3
                ldm4(&bh[0], a0);
                ldm4(&bh[4], a1);
                ldm4(&bl[0], a0 + (BLO_OFF - BHI_OFF));
                ldm4(&bl[4], a1 + (BLO_OFF - BHI_OFF));
            }
#pragma unroll
            for (int mt = 0; mt < 4; mt++) {
                uint32_t aaddr = base + A_OFF +
                    (uint32_t)((aRow + mt*16)*ST + kc*16 + aKoff) * 2;
                uint32_t ah[4];
                ldm4(ah, aaddr);
#pragma unroll
                for (int g = 0; g < 4; g++) {
                    mma16816(accH[mt][g], ah, &bh[g*2]);    // A * Whi   (fp32 acc)
                    mma16816h(accL[mt][g], ah, &bl[g*2]);   // A * Wlo'  (fp16 acc, 2x rate)
                }
            }
        }
    }

    // ---- in-register epilogue ----
    const int cA = wn*8 + (lane & 3)*2;
    const int cg = col0 + cA;
    const float2 br = *(const float2*)&g_b4[cg];
    const float2 bz = *(const float2*)&g_b4[256 + cg];
    const float2 bn = *(const float2*)&g_b4[512 + cg];
    const float2 bm = *(const float2*)&g_b4[768 + cg];
    const float bias[4][2] = {{br.x,br.y},{bz.x,bz.y},{bn.x,bn.y},{bm.x,bm.y}};

#pragma unroll
    for (int mt = 0; mt < 4; mt++) {
        const int rr = row0 + mt*16 + (lane >> 2);
#pragma unroll
        for (int p = 0; p < 2; p++) {
            const int r = rr + p*8;
            float2 hp = *(const float2*)(hprev + (size_t)r*HH + cg);
            float hpv[2] = {hp.x, hp.y};
            // lo-term contributions for this p: half2 = (col j=0, col j=1)
            float2 lo0 = __half22float2(*(__half2*)&accL[mt][0][p]);
            float2 lo1 = __half22float2(*(__half2*)&accL[mt][1][p]);
            float2 lo2 = __half22float2(*(__half2*)&accL[mt][2][p]);
            float2 lo3 = __half22float2(*(__half2*)&accL[mt][3][p]);
            float hn[2];
#pragma unroll
            for (int j = 0; j < 2; j++) {
                int q = p*2 + j;
                float l0 = (j == 0) ? lo0.x : lo0.y;
                float l1 = (j == 0) ? lo1.x : lo1.y;
                float l2 = (j == 0) ? lo2.x : lo2.y;
                float l3 = (j == 0) ? lo3.x : lo3.y;
                float arv = accH[mt][0][q] + l0 * LO_INV + bias[0][j];
                float azv = accH[mt][1][q] + l1 * LO_INV + bias[1][j];
                float anv = accH[mt][2][q] + l2 * LO_INV + bias[2][j];
                float ahv = accH[mt][3][q] + l3 * LO_INV + bias[3][j];
                float rg = 1.f / (1.f + __expf(-arv));
                float zg = 1.f / (1.f + __expf(-azv));
                float x  = anv + rg * ahv;
                float t  = __expf(-2.f * fabsf(x));
                float th = (1.f - t) / (1.f + t);
                th = copysignf(th, x);
                hn[j] = (1.f - zg) * th + zg * hpv[j];
            }
            *(float2*)(hout + (size_t)r*HH + cg) = make_float2(hn[0], hn[1]);
            __half2 h2 = __floats2half2_rn(hn[0], hn[1]);
            *(__half2*)(Oh + (size_t)r*HH + cg) = h2;
        }
    }
}

// ---------------- standalone final out_proj: M=64/CTA, block=128 ----------------
__global__ void __launch_bounds__(128)
out_proj_kernel(const __half* __restrict__ Ah, const float* __restrict__ bout,
                float* __restrict__ y, int step)
{
    extern __shared__ __align__(16) char dsm[];
    const uint32_t sb = smem_u32(dsm);

    const int tid  = threadIdx.x;
    const int lane = tid & 31;
    const int warp = tid >> 5;
    const int row0 = blockIdx.x * 64;

#pragma unroll
    for (int i = 0; i < 16; i++) {
        int e = tid + i * 128;
        int r = e >> 5, seg = e & 31;
        cpa16(sb + OPA_OFF + (uint32_t)(r*OP_ST + seg*8)*2,
              Ah + (size_t)(row0 + r)*HH + seg*8);
    }
#pragma unroll
    for (int i = 0; i < 8; i++) {
        int e = tid + i * 128;
        int r = e >> 5, seg = e & 31;
        cpa16(sb + OPW_OFF + (uint32_t)(r*OP_ST + seg*8)*2,
              g_WoutH + (size_t)r*HH + seg*8);
    }
    asm volatile("cp.async.commit_group;" ::: "memory");
    asm volatile("cp.async.wait_group 0;" ::: "memory");
    __syncthreads();

    const int aRow  = warp*16 + (lane & 15);
    const int aKoff = (lane >> 4) * 8;
    const int bRow  = (lane >> 4) * 8 + (lane & 7);
    const int bKoff = ((lane >> 3) & 1) * 8;

    float acc[4][4];
#pragma unroll
    for (int nt = 0; nt < 4; nt++)
#pragma unroll
        for (int q = 0; q < 4; q++) acc[nt][q] = 0.f;

#pragma unroll
    for (int ks = 0; ks < 16; ks++) {
        uint32_t ah[4], bh[8];
        ldm4(ah, sb + OPA_OFF + (uint32_t)(aRow*OP_ST + ks*16 + aKoff)*2);
#pragma unroll
        for (int p = 0; p < 2; p++)
            ldm4(&bh[p*4], sb + OPW_OFF + (uint32_t)((bRow + p*16)*OP_ST + ks*16 + bKoff)*2);
#pragma unroll
        for (int nt = 0; nt < 4; nt++)
            mma16816(acc[nt], ah, &bh[nt*2]);
    }

    const int rl  = warp*16 + (lane >> 2);
    const int cb  = (lane & 3) * 2;
#pragma unroll
    for (int nt = 0; nt < 4; nt++) {
        int col = nt*8 + cb;
        float b0 = bout[col];
        size_t base0 = (size_t)(row0 + rl) * YSTRIDE + (size_t)step * OUT_;
        size_t base1 = base0 + 8u * YSTRIDE;
        y[base0 + col] = acc[nt][0] + b0;
        y[base1 + col] = acc[nt][2] + b0;
        if (col < 30) {
            float b1 = bout[col + 1];
            y[base0 + col + 1] = acc[nt][1] + b1;
            y[base1 + col + 1] = acc[nt][3] + b1;
        }
    }
}

// ---------------- host ----------------
extern "C" void kernel_launch(void* const* d_in, const int* in_sizes, int n_in,
                              void* d_out, int out_size)
{
    const float* hidden = (const float*)d_in[0];
    const float* Wih    = (const float*)d_in[1];
    const float* Whh    = (const float*)d_in[2];
    const float* bih    = (const float*)d_in[3];
    const float* bhh    = (const float*)d_in[4];
    const float* Wout   = (const float*)d_in[5];
    const float* bout   = (const float*)d_in[6];
    float* y = (float*)d_out;

    __half *pWhi, *pWlo, *pWhi0, *pWlo0, *ps0, *ps1;
    float *phA, *phB;
    cudaGetSymbolAddress((void**)&pWhi,  g_Whi);
    cudaGetSymbolAddress((void**)&pWlo,  g_Wlo);
    cudaGetSymbolAddress((void**)&pWhi0, g_Whi0);
    cudaGetSymbolAddress((void**)&pWlo0, g_Wlo0);
    cudaGetSymbolAddress((void**)&ps0,   g_s0);
    cudaGetSymbolAddress((void**)&ps1,   g_s1);
    cudaGetSymbolAddress((void**)&phA,   g_hA);
    cudaGetSymbolAddress((void**)&phB,   g_hB);

    cudaFuncSetAttribute(gru_mma_kernel, cudaFuncAttributeMaxDynamicSharedMemorySize, SMEM_ALLOC);
    cudaFuncSetAttribute(out_proj_kernel, cudaFuncAttributeMaxDynamicSharedMemorySize, OP_SMEM);

    prep_kernel<<<(4*HH*HH + 255)/256, 256>>>(Wih, Whh, bih, bhh, Wout);
    split_kernel<<<(BB*HH + 255)/256, 256>>>(hidden, ps0);

    dim3 grid(BB/64, 5);   // (256, 4 gru slices + 1 y-projection slice)

    // step 0: x=0 variant; y-slice skips (step==0)
    gru_mma_kernel<<<grid, 256, SMEM_ALLOC>>>(ps0, pWhi0, pWlo0, hidden, phA, ps1,
                                              bout, y, 0);

    float* hin = phA;  float* hot = phB;
    __half *ih = ps1, *oh = ps0;

    for (int t = 1; t < STEPS; t++) {
        gru_mma_kernel<<<grid, 256, SMEM_ALLOC>>>(ih, pWhi, pWlo, hin, hot, oh,
                                                  bout, y, t);
        float* tf = hin; hin = hot; hot = tf;
        __half* th = ih; ih = oh; oh = th;
    }
    // y_119 from final state (in `ih` after last swap)
    out_proj_kernel<<<BB/64, 128, OP_SMEM>>>(ih, bout, y, STEPS - 1);
}

// round 17
// speedup vs baseline: 1.5836x; 1.3095x over previous
#include <cuda_runtime.h>
#include <cuda_fp16.h>
#include <math.h>
#include <stdint.h>

#define BB 16384
#define HH 256
#define STEPS 120
#define OUT_ 31
#define YSTRIDE (STEPS*OUT_)

// ---- gru GEMM: CTA = 64 rows x 256 gate cols; A resident (swizzled), B warp-private 2-stage ----
#define A_OFF   0u          // A: 64 rows x 256 halves, XOR-swizzled, 32768 B
#define B_OFF   32768u      // B: 16 bufs (2 stages x 8 warps) x 5120 B = 81920
#define BWBUF   5120u       // per warp per stage: 64 rows (32 hi + 32 lo) x 40 halves x 2B
#define SMEM_ALLOC 114688   // 2 CTAs/SM target

// ---- fused y-projection (blockIdx.y==4): M=64, N=32, K=256 ----
#define OP_ST 264
#define FYA_OFF 0u
#define FYW_OFF 33792u      // 50688 total <= SMEM_ALLOC

// ---- standalone final out_proj ----
#define OPA_OFF 0u
#define OPW_OFF 33792u
#define OP_SMEM 50688u

// ---------------- device scratch ----------------
__device__ __half g_Whi [4*HH*HH];
__device__ __half g_Wlo [4*HH*HH];
__device__ __half g_Whi0[4*HH*HH];
__device__ __half g_Wlo0[4*HH*HH];
__device__ __half g_WoutH[32*HH];
__device__ float g_b4[4*HH];
__device__ float g_hA[BB*HH];
__device__ float g_hB[BB*HH];
__device__ __half g_s0[BB*HH], g_s1[BB*HH];

// ---------------- PTX helpers (family-safe: sm_80-era only) ----------------
__device__ __forceinline__ uint32_t smem_u32(const void* p) {
    uint32_t a;
    asm("{ .reg .u64 t; cvta.to.shared.u64 t, %1; cvt.u32.u64 %0, t; }" : "=r"(a) : "l"(p));
    return a;
}
__device__ __forceinline__ void cpa16(uint32_t dst, const void* src) {
    asm volatile("cp.async.cg.shared.global [%0], [%1], 16;" :: "r"(dst), "l"(src) : "memory");
}
__device__ __forceinline__ void ldm4(uint32_t* r, uint32_t addr) {
    asm volatile("ldmatrix.sync.aligned.m8n8.x4.shared.b16 {%0,%1,%2,%3}, [%4];"
                 : "=r"(r[0]), "=r"(r[1]), "=r"(r[2]), "=r"(r[3]) : "r"(addr));
}
__device__ __forceinline__ void mma16816(float* c, const uint32_t* a, const uint32_t* b) {
    asm volatile("mma.sync.aligned.m16n8k16.row.col.f32.f16.f16.f32 "
                 "{%0,%1,%2,%3}, {%4,%5,%6,%7}, {%8,%9}, {%0,%1,%2,%3};"
                 : "+f"(c[0]), "+f"(c[1]), "+f"(c[2]), "+f"(c[3])
                 : "r"(a[0]), "r"(a[1]), "r"(a[2]), "r"(a[3]), "r"(b[0]), "r"(b[1]));
}

// ---------------- prep: combined weights, fp16 hi/lo split; Wout fp16 ----------------
__global__ void prep_kernel(const float* __restrict__ Wih, const float* __restrict__ Whh,
                            const float* __restrict__ bih, const float* __restrict__ bhh,
                            const float* __restrict__ Wout)
{
    int idx = blockIdx.x * blockDim.x + threadIdx.x;
    if (idx < 4*HH*HH) {
        int j = idx / HH;
        int k = idx % HH;
        int g = j >> 8, c = j & 255;
        float w, w0;
        if (g == 0)      { float a = Wih[c*HH+k],       b = Whh[c*HH+k];       w = a + b; w0 = b; }
        else if (g == 1) { float a = Wih[(256+c)*HH+k], b = Whh[(256+c)*HH+k]; w = a + b; w0 = b; }
        else if (g == 2) { w = Wih[(512+c)*HH+k]; w0 = 0.f; }
        else             { w = Whh[(512+c)*HH+k]; w0 = w;  }
        __half hi = __float2half_rn(w);
        g_Whi[idx] = hi;
        g_Wlo[idx] = __float2half_rn(w - __half2float(hi));
        __half hi0 = __float2half_rn(w0);
        g_Whi0[idx] = hi0;
        g_Wlo0[idx] = __float2half_rn(w0 - __half2float(hi0));
    }
    if (idx < 32*HH) {
        int o = idx >> 8, k = idx & 255;
        g_WoutH[idx] = __float2half_rn(o < OUT_ ? Wout[o*HH + k] : 0.f);
    }
    if (idx < 4*HH) {
        int g = idx >> 8, c = idx & 255;
        float b;
        if (g == 0)      b = bih[c]     + bhh[c];
        else if (g == 1) b = bih[256+c] + bhh[256+c];
        else if (g == 2) b = bih[512+c];
        else             b = bhh[512+c];
        g_b4[idx] = b;
    }
}

__global__ void split_kernel(const float* __restrict__ h, __half* __restrict__ o)
{
    int idx = blockIdx.x * blockDim.x + threadIdx.x;
    if (idx < BB*HH) o[idx] = __float2half_rn(h[idx]);
}

// ---------------- fused GRU step + previous-step y projection ----------------
// grid = (256, 5), 256 threads (8 warps), 2 CTAs/SM.
// gru: A resident in smem (1 barrier), B warp-private 2-stage cp.async -> NO mainloop barriers.
__global__ void __launch_bounds__(256, 2)
gru_mma_kernel(const __half* __restrict__ Ah,
               const __half* __restrict__ Whi, const __half* __restrict__ Wlo,
               const float* __restrict__ hprev, float* __restrict__ hout,
               __half* __restrict__ Oh,
               const float* __restrict__ bout, float* __restrict__ y, int step)
{
    extern __shared__ __align__(16) char dsm[];
    const uint32_t sb = smem_u32(dsm);

    const int tid  = threadIdx.x;
    const int lane = tid & 31;
    const int warp = tid >> 5;
    const int row0 = blockIdx.x * 64;

    if (blockIdx.y == 4) {
        // ---------- y-projection block: M=64, N=32, K=256 ----------
        if (step == 0) return;
#pragma unroll
        for (int i = 0; i < 8; i++) {
            int e = tid + i * 256;
            int r = e >> 5, seg = e & 31;
            cpa16(sb + FYA_OFF + (uint32_t)(r*OP_ST + seg*8)*2,
                  Ah + (size_t)(row0 + r)*HH + seg*8);
        }
#pragma unroll
        for (int i = 0; i < 4; i++) {
            int e = tid + i * 256;
            int r = e >> 5, seg = e & 31;
            cpa16(sb + FYW_OFF + (uint32_t)(r*OP_ST + seg*8)*2,
                  g_WoutH + (size_t)r*HH + seg*8);
        }
        asm volatile("cp.async.commit_group;" ::: "memory");
        asm volatile("cp.async.wait_group 0;" ::: "memory");
        __syncthreads();

        const int mt = warp >> 1;
        const int nh = warp & 1;
        const int aRow  = mt*16 + (lane & 15);
        const int aKoff = (lane >> 4) * 8;
        const int bRow  = nh*16 + (lane >> 4) * 8 + (lane & 7);
        const int bKoff = ((lane >> 3) & 1) * 8;

        float acc[2][4];
#pragma unroll
        for (int nt = 0; nt < 2; nt++)
#pragma unroll
            for (int q = 0; q < 4; q++) acc[nt][q] = 0.f;

#pragma unroll
        for (int ks = 0; ks < 16; ks++) {
            uint32_t ah[4], bh[4];
            ldm4(ah, sb + FYA_OFF + (uint32_t)(aRow*OP_ST + ks*16 + aKoff)*2);
            ldm4(bh, sb + FYW_OFF + (uint32_t)(bRow*OP_ST + ks*16 + bKoff)*2);
#pragma unroll
            for (int nt = 0; nt < 2; nt++)
                mma16816(acc[nt], ah, &bh[nt*2]);
        }

        const int rl = mt*16 + (lane >> 2);
        const int cb = (lane & 3) * 2;
#pragma unroll
        for (int nt = 0; nt < 2; nt++) {
            int col = nh*16 + nt*8 + cb;
            float b0 = bout[col];
            size_t base0 = (size_t)(row0 + rl) * YSTRIDE + (size_t)(step - 1) * OUT_;
            size_t base1 = base0 + 8u * YSTRIDE;
            y[base0 + col] = acc[nt][0] + b0;
            y[base1 + col] = acc[nt][2] + b0;
            if (col < 30) {
                float b1 = bout[col + 1];
                y[base0 + col + 1] = acc[nt][1] + b1;
                y[base1 + col + 1] = acc[nt][3] + b1;
            }
        }
        return;
    }

    // ---------- gru GEMM block ----------
    const int wn   = warp;             // 0..7 -> hidden col chunk wn*8
    const int col0 = blockIdx.y * 64;

    // ---- issue A tile load (group 0): 64 rows x 256 halves, XOR swizzle (u ^= row&7) ----
#pragma unroll
    for (int i = 0; i < 8; i++) {
        int e = tid + i * 256;         // 0..2047 16B chunks
        int r = e >> 5, u = e & 31;
        uint32_t du = (uint32_t)(u ^ (r & 7));
        cpa16(sb + A_OFF + (uint32_t)(r*256 + du*8)*2,
              Ah + (size_t)(row0 + r)*HH + u*8);
    }
    asm volatile("cp.async.commit_group;" ::: "memory");

    // ---- warp-private B stage loader (this warp's 32 gate rows, hi rows 0-31, lo rows 32-63) ----
    auto load_B = [&](int s) {
        const uint32_t wb = sb + B_OFF + (uint32_t)((s & 1)*8 + wn) * BWBUF;
        const int kb = s * 32;
#pragma unroll
        for (int i = 0; i < 8; i++) {
            int e = lane + i * 32;     // 0..255 16B chunks
            int row = e >> 2, seg = e & 3;
            int rr = row & 31;
            int j = ((rr >> 3) << 8) + col0 + wn*8 + (rr & 7);
            const __half* src = (row < 32) ? (Whi + (size_t)j*HH + kb + seg*8)
                                           : (Wlo + (size_t)j*HH + kb + seg*8);
            cpa16(wb + (uint32_t)(row*40 + seg*8)*2, src);
        }
    };

    load_B(0);
    asm volatile("cp.async.commit_group;" ::: "memory");   // group 1
    load_B(1);
    asm volatile("cp.async.commit_group;" ::: "memory");   // group 2

    // A arrival: one block barrier for the whole kernel
    asm volatile("cp.async.wait_group 2;" ::: "memory");
    __syncthreads();

    const int aRowB = lane & 15;       // A frag row within 16-block
    const int aKsel = lane >> 4;       // 0,1 -> k-half (8 halves)
    const int lg = lane >> 3, lr = lane & 7;

    float acc[4][4][4];   // [mt][gate][q]
#pragma unroll
    for (int mt = 0; mt < 4; mt++)
#pragma unroll
        for (int g = 0; g < 4; g++)
#pragma unroll
            for (int q = 0; q < 4; q++) acc[mt][g][q] = 0.f;

    for (int s = 0; s < 8; s++) {
        // Ledger: committed at this point = 3 + min(s,6) groups (A + B0..B_{min(s,6)+1}).
        // s<7: wait_group 1 leaves only the newest (B_{s+1}) possibly in flight -> B_s landed.
        // s==7: newest IS B7 -> must drain fully.
        if (s < 7) asm volatile("cp.async.wait_group 1;" ::: "memory");
        else       asm volatile("cp.async.wait_group 0;" ::: "memory");
        __syncwarp();
        const uint32_t wb = sb + B_OFF + (uint32_t)((s & 1)*8 + wn) * BWBUF;

#pragma unroll
        for (int kc = 0; kc < 2; kc++) {
            uint32_t bh[8], bl[8];
            {
                // lg: gate (lg>>1) in {0,1}, k-half (lg&1); 2nd ldm4 -> gates 2,3; lo at +2560B
                uint32_t a0 = wb + (uint32_t)((((lg >> 1)*8) + lr)*40 + kc*16 + (lg & 1)*8) * 2;
                ldm4(&bh[0], a0);
                ldm4(&bh[4], a0 + (uint32_t)(16*40)*2);
                ldm4(&bl[0], a0 + 2560u);
                ldm4(&bl[4], a0 + 2560u + (uint32_t)(16*40)*2);
            }
#pragma unroll
            for (int mt = 0; mt < 4; mt++) {
                int R = mt*16 + aRowB;
                uint32_t u = (uint32_t)(s*4 + kc*2 + aKsel) ^ (uint32_t)(R & 7);
                uint32_t aaddr = sb + A_OFF + (uint32_t)(R*256 + u*8) * 2;
                uint32_t ah[4];
                ldm4(ah, aaddr);
#pragma unroll
                for (int g = 0; g < 4; g++) {
                    mma16816(acc[mt][g], ah, &bh[g*2]);   // A * Whi
                    mma16816(acc[mt][g], ah, &bl[g*2]);   // A * Wlo
                }
            }
        }

        if (s < 6) {                    // prefetch s+2 into the buffer just freed
            load_B(s + 2);
            asm volatile("cp.async.commit_group;" ::: "memory");
        }
    }

    // ---- in-register epilogue ----
    const int cA = wn*8 + (lane & 3)*2;
    const int cg = col0 + cA;
    const float2 br = *(const float2*)&g_b4[cg];
    const float2 bz = *(const float2*)&g_b4[256 + cg];
    const float2 bn = *(const float2*)&g_b4[512 + cg];
    const float2 bm = *(const float2*)&g_b4[768 + cg];
    const float bias[4][2] = {{br.x,br.y},{bz.x,bz.y},{bn.x,bn.y},{bm.x,bm.y}};

#pragma unroll
    for (int mt = 0; mt < 4; mt++) {
        const int rr = row0 + mt*16 + (lane >> 2);
#pragma unroll
        for (int p = 0; p < 2; p++) {
            const int r = rr + p*8;
            float2 hp = *(const float2*)(hprev + (size_t)r*HH + cg);
            float hpv[2] = {hp.x, hp.y};
            float hn[2];
#pragma unroll
            for (int j = 0; j < 2; j++) {
                int q = p*2 + j;
                float arv = acc[mt][0][q] + bias[0][j];
                float azv = acc[mt][1][q] + bias[1][j];
                float anv = acc[mt][2][q] + bias[2][j];
                float ahv = acc[mt][3][q] + bias[3][j];
                float rg = 1.f / (1.f + __expf(-arv));
                float zg = 1.f / (1.f + __expf(-azv));
                float x  = anv + rg * ahv;
                float t  = __expf(-2.f * fabsf(x));
                float th = (1.f - t) / (1.f + t);
                th = copysignf(th, x);
                hn[j] = (1.f - zg) * th + zg * hpv[j];
            }
            *(float2*)(hout + (size_t)r*HH + cg) = make_float2(hn[0], hn[1]);
            __half2 h2 = __floats2half2_rn(hn[0], hn[1]);
            *(__half2*)(Oh + (size_t)r*HH + cg) = h2;
        }
    }
}

// ---------------- standalone final out_proj: M=64/CTA, block=128 ----------------
__global__ void __launch_bounds__(128)
out_proj_kernel(const __half* __restrict__ Ah, const float* __restrict__ bout,
                float* __restrict__ y, int step)
{
    extern __shared__ __align__(16) char dsm[];
    const uint32_t sb = smem_u32(dsm);

    const int tid  = threadIdx.x;
    const int lane = tid & 31;
    const int warp = tid >> 5;
    const int row0 = blockIdx.x * 64;

#pragma unroll
    for (int i = 0; i < 16; i++) {
        int e = tid + i * 128;
        int r = e >> 5, seg = e & 31;
        cpa16(sb + OPA_OFF + (uint32_t)(r*OP_ST + seg*8)*2,
              Ah + (size_t)(row0 + r)*HH + seg*8);
    }
#pragma unroll
    for (int i = 0; i < 8; i++) {
        int e = tid + i * 128;
        int r = e >> 5, seg = e & 31;
        cpa16(sb + OPW_OFF + (uint32_t)(r*OP_ST + seg*8)*2,
              g_WoutH + (size_t)r*HH + seg*8);
    }
    asm volatile("cp.async.commit_group;" ::: "memory");
    asm volatile("cp.async.wait_group 0;" ::: "memory");
    __syncthreads();

    const int aRow  = warp*16 + (lane & 15);
    const int aKoff = (lane >> 4) * 8;
    const int bRow  = (lane >> 4) * 8 + (lane & 7);
    const int bKoff = ((lane >> 3) & 1) * 8;

    float acc[4][4];
#pragma unroll
    for (int nt = 0; nt < 4; nt++)
#pragma unroll
        for (int q = 0; q < 4; q++) acc[nt][q] = 0.f;

#pragma unroll
    for (int ks = 0; ks < 16; ks++) {
        uint32_t ah[4], bh[8];
        ldm4(ah, sb + OPA_OFF + (uint32_t)(aRow*OP_ST + ks*16 + aKoff)*2);
#pragma unroll
        for (int p = 0; p < 2; p++)
            ldm4(&bh[p*4], sb + OPW_OFF + (uint32_t)((bRow + p*16)*OP_ST + ks*16 + bKoff)*2);
#pragma unroll
        for (int nt = 0; nt < 4; nt++)
            mma16816(acc[nt], ah, &bh[nt*2]);
    }

    const int rl  = warp*16 + (lane >> 2);
    const int cb  = (lane & 3) * 2;
#pragma unroll
    for (int nt = 0; nt < 4; nt++) {
        int col = nt*8 + cb;
        float b0 = bout[col];
        size_t base0 = (size_t)(row0 + rl) * YSTRIDE + (size_t)step * OUT_;
        size_t base1 = base0 + 8u * YSTRIDE;
        y[base0 + col] = acc[nt][0] + b0;
        y[base1 + col] = acc[nt][2] + b0;
        if (col < 30) {
            float b1 = bout[col + 1];
            y[base0 + col + 1] = acc[nt][1] + b1;
            y[base1 + col + 1] = acc[nt][3] + b1;
        }
    }
}

// ---------------- host ----------------
extern "C" void kernel_launch(void* const* d_in, const int* in_sizes, int n_in,
                              void* d_out, int out_size)
{
    const float* hidden = (const float*)d_in[0];
    const float* Wih    = (const float*)d_in[1];
    const float* Whh    = (const float*)d_in[2];
    const float* bih    = (const float*)d_in[3];
    const float* bhh    = (const float*)d_in[4];
    const float* Wout   = (const float*)d_in[5];
    const float* bout   = (const float*)d_in[6];
    float* y = (float*)d_out;

    __half *pWhi, *pWlo, *pWhi0, *pWlo0, *ps0, *ps1;
    float *phA, *phB;
    cudaGetSymbolAddress((void**)&pWhi,  g_Whi);
    cudaGetSymbolAddress((void**)&pWlo,  g_Wlo);
    cudaGetSymbolAddress((void**)&pWhi0, g_Whi0);
    cudaGetSymbolAddress((void**)&pWlo0, g_Wlo0);
    cudaGetSymbolAddress((void**)&ps0,   g_s0);
    cudaGetSymbolAddress((void**)&ps1,   g_s1);
    cudaGetSymbolAddress((void**)&phA,   g_hA);
    cudaGetSymbolAddress((void**)&phB,   g_hB);

    cudaFuncSetAttribute(gru_mma_kernel, cudaFuncAttributeMaxDynamicSharedMemorySize, SMEM_ALLOC);
    cudaFuncSetAttribute(out_proj_kernel, cudaFuncAttributeMaxDynamicSharedMemorySize, OP_SMEM);

    prep_kernel<<<(4*HH*HH + 255)/256, 256>>>(Wih, Whh, bih, bhh, Wout);
    split_kernel<<<(BB*HH + 255)/256, 256>>>(hidden, ps0);

    dim3 grid(BB/64, 5);   // (256, 4 gru slices + 1 y-projection slice)

    gru_mma_kernel<<<grid, 256, SMEM_ALLOC>>>(ps0, pWhi0, pWlo0, hidden, phA, ps1,
                                              bout, y, 0);

    float* hin = phA;  float* hot = phB;
    __half *ih = ps1, *oh = ps0;

    for (int t = 1; t < STEPS; t++) {
        gru_mma_kernel<<<grid, 256, SMEM_ALLOC>>>(ih, pWhi, pWlo, hin, hot, oh,
                                                  bout, y, t);
        float* tf = hin; hin = hot; hot = tf;
        __half* th = ih; ih = oh; oh = th;
    }
    out_proj_kernel<<<BB/64, 128, OP_SMEM>>>(ih, bout, y, STEPS - 1);
}